// round 13
// baseline (speedup 1.0000x reference)
#include <cuda_runtime.h>
#include <cuda_fp16.h>
#include <cstdint>
#include <cstddef>

#define NR 2048
#define NC 32
#define NO 32
#define NI 32
#define NB 64
#define NCO (NC*NO)        // 1024
#define RSTRIDE (NCO*NB)   // 65536 halves per route in u_hat
#define C_UNI (1.0f/2048.0f)
#define NRCH 128           // route chunks of 16 in the fused kernel

// Scratch (device globals: allocation-free contract)
__device__ __half g_uhat[(size_t)NR * NCO * NB]; // [r][c][o][b]  268 MB fp16
__device__ float  g_spart0[(size_t)NRCH * NCO * NB]; // fused s0 partials 32 MB
__device__ float  g_spart[512 * 4 * 128];        // k_s partials [co2][q][128]
__device__ float  g_blog[NC * NR];               // routing logits b_ij [c][r]
__device__ float  g_cij[NC * NR];                // softmax(b) over r, [c][r]
__device__ float  g_v2[NCO * NB];                // v in [c][o][b] layout

// ---------------------------------------------------------------------------
__device__ __forceinline__ uint32_t pack_f16x2(float a, float b) {
    uint32_t r;
    asm("cvt.rn.f16x2.f32 %0, %1, %2;" : "=r"(r) : "f"(b), "f"(a));
    return r;
}
// D += A*B (m16n8k16, fp16 in, fp32 acc) — plain mma.sync
__device__ __forceinline__ void mma16816(float* c, const uint32_t* a,
                                         uint32_t b0, uint32_t b1) {
    asm volatile(
        "mma.sync.aligned.m16n8k16.row.col.f32.f16.f16.f32 "
        "{%0,%1,%2,%3},{%4,%5,%6,%7},{%8,%9},{%0,%1,%2,%3};"
        : "+f"(c[0]), "+f"(c[1]), "+f"(c[2]), "+f"(c[3])
        : "r"(a[0]), "r"(a[1]), "r"(a[2]), "r"(a[3]), "r"(b0), "r"(b1));
}

// ---------------------------------------------------------------------------
// FUSED: u_hat production + iteration-0 s accumulation (c_ij == 1/2048 exact).
// Grid (rchunk=128, cochunk=8). Block 256: warp w owns m16 tile
// co0 = cochunk*128 + w*16; iterates 16 routes, accumulating C_UNI * u in regs.
__global__ void __launch_bounds__(256) k_us0(const float* __restrict__ x,
                                             const float* __restrict__ W) {
    const int rch  = blockIdx.x;
    const int cch  = blockIdx.y;
    const int tid  = threadIdx.x;
    const int w    = tid >> 5;
    const int lane = tid & 31;
    const int g    = lane >> 2;
    const int tg   = lane & 3;
    const int co0  = cch * 128 + w * 16 + g;   // rows co0 and co0+8

    float acc[8][4];
#pragma unroll
    for (int nt = 0; nt < 8; ++nt)
#pragma unroll
        for (int j = 0; j < 4; ++j) acc[nt][j] = 0.f;

#pragma unroll 1
    for (int it = 0; it < 16; ++it) {
        const int r = rch * 16 + it;

        // B fragments for x_r (shared across warps via L1/L2)
        uint32_t B[8][2][2];
#pragma unroll
        for (int nt = 0; nt < 8; ++nt) {
            const float* xr = x + (size_t)(nt * 8 + g) * (NR * NI) + (size_t)r * NI;
#pragma unroll
            for (int ks = 0; ks < 2; ++ks) {
                const float2 v0 = *(const float2*)(xr + ks * 16 + 2 * tg);
                const float2 v1 = *(const float2*)(xr + ks * 16 + 2 * tg + 8);
                B[nt][ks][0] = pack_f16x2(v0.x, v0.y);
                B[nt][ks][1] = pack_f16x2(v1.x, v1.y);
            }
        }

        // A fragments for W[r] tile rows co0, co0+8
        const float* wr0 = W + (size_t)r * (NCO * NI) + (size_t)co0 * NI;
        const float* wr1 = wr0 + 8 * NI;
        uint32_t A[2][4];
#pragma unroll
        for (int ks = 0; ks < 2; ++ks) {
            float2 v;
            v = *(const float2*)(wr0 + ks * 16 + 2 * tg);     A[ks][0] = pack_f16x2(v.x, v.y);
            v = *(const float2*)(wr1 + ks * 16 + 2 * tg);     A[ks][1] = pack_f16x2(v.x, v.y);
            v = *(const float2*)(wr0 + ks * 16 + 2 * tg + 8); A[ks][2] = pack_f16x2(v.x, v.y);
            v = *(const float2*)(wr1 + ks * 16 + 2 * tg + 8); A[ks][3] = pack_f16x2(v.x, v.y);
        }

        __half* const ubase = g_uhat + (size_t)r * RSTRIDE;
#pragma unroll
        for (int nt = 0; nt < 8; ++nt) {
            float t4[4] = {0.f, 0.f, 0.f, 0.f};
            mma16816(t4, A[0], B[nt][0][0], B[nt][0][1]);
            mma16816(t4, A[1], B[nt][1][0], B[nt][1][1]);
            const int b0 = nt * 8 + 2 * tg;
            *(__half2*)(ubase + (size_t)co0 * NB + b0) =
                __floats2half2_rn(t4[0], t4[1]);
            *(__half2*)(ubase + (size_t)(co0 + 8) * NB + b0) =
                __floats2half2_rn(t4[2], t4[3]);
#pragma unroll
            for (int j = 0; j < 4; ++j)
                acc[nt][j] = fmaf(C_UNI, t4[j], acc[nt][j]);
        }
    }

    // write s0 partials for this route chunk
    float* sp = g_spart0 + (size_t)rch * (NCO * NB);
#pragma unroll
    for (int nt = 0; nt < 8; ++nt) {
        const int b0 = nt * 8 + 2 * tg;
        *(float2*)(sp + co0 * NB + b0)       = make_float2(acc[nt][0], acc[nt][1]);
        *(float2*)(sp + (co0 + 8) * NB + b0) = make_float2(acc[nt][2], acc[nt][3]);
    }
}

// ---------------------------------------------------------------------------
// Reduce s0 partials over 128 route chunks, squash -> g_v2.
__global__ void __launch_bounds__(256) k_red0() {
    const int idx = blockIdx.x * 256 + threadIdx.x;   // co*64 + b  (65536)
    const float* p = g_spart0 + idx;
    float s = 0.f;
#pragma unroll 8
    for (int k = 0; k < NRCH; ++k) s += p[(size_t)k * (NCO * NB)];
    const float sq = s * s;
    g_v2[idx] = sq * s / ((1.f + sq) * sqrtf(sq));
}

// ---------------------------------------------------------------------------
// c_ij[c][:] = softmax over r of b[c][:]. One block per capsule c; contiguous.
__global__ void __launch_bounds__(256) k_softmax() {
    const int c   = blockIdx.x;
    const int tid = threadIdx.x;
    __shared__ float sm[8];
    const float* bp = g_blog + c * NR;

    float vals[8];
#pragma unroll
    for (int j = 0; j < 8; ++j) vals[j] = bp[tid + j * 256];

    float m = vals[0];
#pragma unroll
    for (int j = 1; j < 8; ++j) m = fmaxf(m, vals[j]);
#pragma unroll
    for (int off = 16; off; off >>= 1) m = fmaxf(m, __shfl_xor_sync(0xffffffffu, m, off));
    if ((tid & 31) == 0) sm[tid >> 5] = m;
    __syncthreads();
    float mm = sm[0];
#pragma unroll
    for (int j = 1; j < 8; ++j) mm = fmaxf(mm, sm[j]);
    __syncthreads();

    float e[8];
    float s = 0.f;
#pragma unroll
    for (int j = 0; j < 8; ++j) { e[j] = expf(vals[j] - mm); s += e[j]; }
#pragma unroll
    for (int off = 16; off; off >>= 1) s += __shfl_xor_sync(0xffffffffu, s, off);
    if ((tid & 31) == 0) sm[tid >> 5] = s;
    __syncthreads();
    float tot = 0.f;
#pragma unroll
    for (int j = 0; j < 8; ++j) tot += sm[j];
    const float inv = 1.f / tot;
    float* cp = g_cij + c * NR;
#pragma unroll
    for (int j = 0; j < 8; ++j) cp[tid + j * 256] = e[j] * inv;
}

// ---------------------------------------------------------------------------
// s partial: block (co2, q) covers routes [q*512, +512). (R10/R12 form.)
__global__ void __launch_bounds__(256) k_s() {
    const int co2 = blockIdx.x;
    const int q   = blockIdx.y;
    const int c   = co2 >> 4;
    const int tid = threadIdx.x;
    __shared__ float cs[512];
    __shared__ float red[8][128];

#pragma unroll
    for (int j = 0; j < 2; ++j)
        cs[tid + j * 256] = g_cij[c * NR + q * 512 + tid + j * 256];
    __syncthreads();

    const int seg  = tid >> 5;
    const int lane = tid & 31;
    const int co_l = lane >> 4;
    const int b4   = (lane & 15) * 4;
    const int r0   = q * 512 + seg * 64;
    const uint2* p = (const uint2*)(g_uhat + (size_t)r0 * RSTRIDE
                                    + (size_t)co2 * 128 + co_l * 64 + b4);
    const float* csp = cs + seg * 64;

    float a0 = 0.f, a1 = 0.f, a2 = 0.f, a3 = 0.f;
#pragma unroll 16
    for (int k = 0; k < 64; ++k) {
        const uint2 u = __ldcs(&p[(size_t)k * (RSTRIDE / 4)]);
        const float2 f0 = __half22float2(*(const __half2*)&u.x);
        const float2 f1 = __half22float2(*(const __half2*)&u.y);
        const float cc = csp[k];
        a0 = fmaf(cc, f0.x, a0);
        a1 = fmaf(cc, f0.y, a1);
        a2 = fmaf(cc, f1.x, a2);
        a3 = fmaf(cc, f1.y, a3);
    }
    red[seg][co_l * 64 + b4 + 0] = a0;
    red[seg][co_l * 64 + b4 + 1] = a1;
    red[seg][co_l * 64 + b4 + 2] = a2;
    red[seg][co_l * 64 + b4 + 3] = a3;
    __syncthreads();

    if (tid < 128) {
        float s = 0.f;
#pragma unroll
        for (int j = 0; j < 8; ++j) s += red[j][tid];
        g_spart[(co2 * 4 + q) * 128 + tid] = s;
    }
}

// ---------------------------------------------------------------------------
// Combine quarters, squash -> g_v2 (+ final output on last iter).
__global__ void __launch_bounds__(256) k_red(float* __restrict__ outp) {
    const int idx = blockIdx.x * 256 + threadIdx.x;
    const int co2 = idx >> 7, e = idx & 127;
    const float* pp = g_spart + co2 * 4 * 128 + e;
    const float s = (pp[0] + pp[128]) + (pp[256] + pp[384]);
    const int co = co2 * 2 + (e >> 6);
    const int b  = e & 63;
    const float sq = s * s;
    const float v  = sq * s / ((1.f + sq) * sqrtf(sq));
    g_v2[co * NB + b] = v;
    if (outp) outp[b * NCO + co] = v;
}

// ---------------------------------------------------------------------------
// b[c][r] (+)= (1/B) * sum_{b,o} u_hat[r][c][o][b] * v[c][o][b].
// Warp = (route-group rg of 16, o-quarter oq); 2-deep software pipeline.
__global__ void __launch_bounds__(256) k_a(int first) {
    const int c    = blockIdx.y;
    const int r0   = blockIdx.x * 32;
    const int tid  = threadIdx.x;
    const int lane = tid & 31;
    const int w    = tid >> 5;
    const int oq   = w & 3;
    const int rg   = w >> 2;
    __shared__ __align__(16) float vsm[NO * NB];  // 8 KB
    __shared__ float a_sm[32];

    const float4* vsrc = (const float4*)(g_v2 + c * (NO * NB));
    float4* vdst = (float4*)vsm;
#pragma unroll
    for (int j = 0; j < 2; ++j) vdst[tid + j * 256] = vsrc[tid + j * 256];
    if (tid < 32) a_sm[tid] = 0.f;
    __syncthreads();

    float4 vr[4];
#pragma unroll
    for (int k = 0; k < 2; ++k) {
        const int s = oq * 64 + k * 32 + lane;
        vr[2 * k]     = ((const float4*)vsm)[2 * s];
        vr[2 * k + 1] = ((const float4*)vsm)[2 * s + 1];
    }

    const uint4* const ubase =
        (const uint4*)(g_uhat + (size_t)r0 * RSTRIDE + c * (NO * NB))
        + oq * 64 + lane;
    const size_t rstep = RSTRIDE / 8;

    uint4 u0 = __ldcs(ubase + (size_t)(rg * 16) * rstep);
    uint4 u1 = __ldcs(ubase + (size_t)(rg * 16) * rstep + 32);

#pragma unroll 4
    for (int it = 0; it < 16; ++it) {
        const int rl = rg * 16 + it;
        uint4 n0, n1;
        if (it < 15) {
            n0 = __ldcs(ubase + (size_t)(rl + 1) * rstep);
            n1 = __ldcs(ubase + (size_t)(rl + 1) * rstep + 32);
        }
        float p = 0.f;
        {
            const float2 f0 = __half22float2(*(const __half2*)&u0.x);
            const float2 f1 = __half22float2(*(const __half2*)&u0.y);
            const float2 f2 = __half22float2(*(const __half2*)&u0.z);
            const float2 f3 = __half22float2(*(const __half2*)&u0.w);
            p = fmaf(f0.x, vr[0].x, p); p = fmaf(f0.y, vr[0].y, p);
            p = fmaf(f1.x, vr[0].z, p); p = fmaf(f1.y, vr[0].w, p);
            p = fmaf(f2.x, vr[1].x, p); p = fmaf(f2.y, vr[1].y, p);
            p = fmaf(f3.x, vr[1].z, p); p = fmaf(f3.y, vr[1].w, p);
        }
        {
            const float2 f0 = __half22float2(*(const __half2*)&u1.x);
            const float2 f1 = __half22float2(*(const __half2*)&u1.y);
            const float2 f2 = __half22float2(*(const __half2*)&u1.z);
            const float2 f3 = __half22float2(*(const __half2*)&u1.w);
            p = fmaf(f0.x, vr[2].x, p); p = fmaf(f0.y, vr[2].y, p);
            p = fmaf(f1.x, vr[2].z, p); p = fmaf(f1.y, vr[2].w, p);
            p = fmaf(f2.x, vr[3].x, p); p = fmaf(f2.y, vr[3].y, p);
            p = fmaf(f3.x, vr[3].z, p); p = fmaf(f3.y, vr[3].w, p);
        }
        u0 = n0; u1 = n1;
#pragma unroll
        for (int off = 16; off; off >>= 1) p += __shfl_xor_sync(0xffffffffu, p, off);
        if (lane == 0) atomicAdd(&a_sm[rl], p);
    }
    __syncthreads();

    if (tid < 32) {
        const float val = a_sm[tid] * (1.f / NB);
        if (first) g_blog[c * NR + r0 + tid] = val;
        else       g_blog[c * NR + r0 + tid] += val;
    }
}

// ---------------------------------------------------------------------------
extern "C" void kernel_launch(void* const* d_in, const int* in_sizes, int n_in,
                              void* d_out, int out_size) {
    const float* x = (const float*)d_in[0];  // [B, R, I]
    const float* W = (const float*)d_in[1];  // [R, C, O, I]
    if (n_in >= 2 && in_sizes[0] > in_sizes[1]) {  // robust to input ordering
        const float* t = x; x = W; W = t;
    }
    float* out = (float*)d_out;

    // iteration 0 fused: u_hat + s0 (c_ij == 1/2048 exactly)
    k_us0<<<dim3(NRCH, 8), 256>>>(x, W);
    k_red0<<<256, 256>>>();
    k_a<<<dim3(64, 32), 256>>>(1);

    // iteration 1
    k_softmax<<<NC, 256>>>();
    k_s<<<dim3(512, 4), 256>>>();
    k_red<<<256, 256>>>(nullptr);
    k_a<<<dim3(64, 32), 256>>>(0);

    // iteration 2 (final)
    k_softmax<<<NC, 256>>>();
    k_s<<<dim3(512, 4), 256>>>();
    k_red<<<256, 256>>>(out);
}

// round 14
// speedup vs baseline: 1.7177x; 1.7177x over previous
#include <cuda_runtime.h>
#include <cuda_fp16.h>
#include <cstdint>
#include <cstddef>

#define NR 2048
#define NC 32
#define NO 32
#define NI 32
#define NB 64
#define NCO (NC*NO)        // 1024
#define RSTRIDE (NCO*NB)   // 65536 halves per route in u_hat
#define C_UNI (1.0f/2048.0f)
#define TPAD 72            // padded smem tile row stride (halves)

// Scratch (device globals: allocation-free contract)
__device__ __half g_uhat[(size_t)NR * NCO * NB]; // [r][c][o][b]  268 MB fp16
__device__ float  g_spart[512 * 4 * 128];        // k_s partials [co2][q][128]
__device__ float  g_blog[NC * NR];               // routing logits b_ij [c][r]
__device__ float  g_cij[NC * NR];                // softmax(b) over r, [c][r]
__device__ float  g_v2[NCO * NB];                // v in [c][o][b] layout

// ---------------------------------------------------------------------------
__device__ __forceinline__ uint32_t pack_f16x2(float a, float b) {
    uint32_t r;
    asm("cvt.rn.f16x2.f32 %0, %1, %2;" : "=r"(r) : "f"(b), "f"(a));
    return r;
}
// D += A*B (m16n8k16, fp16 in, fp32 acc) — plain mma.sync
__device__ __forceinline__ void mma16816(float* c, const uint32_t* a,
                                         uint32_t b0, uint32_t b1) {
    asm volatile(
        "mma.sync.aligned.m16n8k16.row.col.f32.f16.f16.f32 "
        "{%0,%1,%2,%3},{%4,%5,%6,%7},{%8,%9},{%0,%1,%2,%3};"
        : "+f"(c[0]), "+f"(c[1]), "+f"(c[2]), "+f"(c[3])
        : "r"(a[0]), "r"(a[1]), "r"(a[2]), "r"(a[3]), "r"(b0), "r"(b1));
}

// ---------------------------------------------------------------------------
// u_hat via mma.sync: per route r, D[1024co x 64b] = W_r[1024x32] @ x_r^T.
// Block = route r (B fragments in regs for whole block). Stores are staged
// through a padded smem tile per warp, then written as 2048 contiguous bytes
// (full-sector coalescing; the direct fragment stores were ~50% efficient).
__global__ void __launch_bounds__(256) k_uhat(const float* __restrict__ x,
                                              const float* __restrict__ W) {
    __shared__ __half tile[8][16 * TPAD];   // 8 warps x 16 rows x 72 halves
    const int r    = blockIdx.x;
    const int tid  = threadIdx.x;
    const int w    = tid >> 5;
    const int lane = tid & 31;
    const int g    = lane >> 2;
    const int tg   = lane & 3;

    uint32_t B[8][2][2];
#pragma unroll
    for (int nt = 0; nt < 8; ++nt) {
        const float* xr = x + (size_t)(nt * 8 + g) * (NR * NI) + (size_t)r * NI;
#pragma unroll
        for (int ks = 0; ks < 2; ++ks) {
            const float2 v0 = *(const float2*)(xr + ks * 16 + 2 * tg);
            const float2 v1 = *(const float2*)(xr + ks * 16 + 2 * tg + 8);
            B[nt][ks][0] = pack_f16x2(v0.x, v0.y);
            B[nt][ks][1] = pack_f16x2(v1.x, v1.y);
        }
    }

    const float* wbase = W + (size_t)r * (NCO * NI);
    __half* const ubase = g_uhat + (size_t)r * RSTRIDE;

#pragma unroll 1
    for (int mt = 0; mt < 8; ++mt) {
        const int co0 = w * 128 + mt * 16 + g;
        const float* wr0 = wbase + (size_t)co0 * NI;
        const float* wr1 = wr0 + 8 * NI;

        uint32_t A[2][4];
#pragma unroll
        for (int ks = 0; ks < 2; ++ks) {
            float2 v;
            v = *(const float2*)(wr0 + ks * 16 + 2 * tg);     A[ks][0] = pack_f16x2(v.x, v.y);
            v = *(const float2*)(wr1 + ks * 16 + 2 * tg);     A[ks][1] = pack_f16x2(v.x, v.y);
            v = *(const float2*)(wr0 + ks * 16 + 2 * tg + 8); A[ks][2] = pack_f16x2(v.x, v.y);
            v = *(const float2*)(wr1 + ks * 16 + 2 * tg + 8); A[ks][3] = pack_f16x2(v.x, v.y);
        }

        __half* const tw = tile[w];
#pragma unroll
        for (int nt = 0; nt < 8; ++nt) {
            float acc[4] = {0.f, 0.f, 0.f, 0.f};
            mma16816(acc, A[0], B[nt][0][0], B[nt][0][1]);
            mma16816(acc, A[1], B[nt][1][0], B[nt][1][1]);
            const int b0 = nt * 8 + 2 * tg;
            // STS banks: (4g + 4nt + tg) % 32 — conflict-free per instruction
            *(__half2*)(tw + g * TPAD + b0)       = __floats2half2_rn(acc[0], acc[1]);
            *(__half2*)(tw + (g + 8) * TPAD + b0) = __floats2half2_rn(acc[2], acc[3]);
        }
        __syncwarp();

        // Tile rows co = w*128 + mt*16 .. +16 are CONTIGUOUS in global
        // (row stride 64 halves = 128B): write 2048B coalesced.
        uint4* dst = (uint4*)(ubase + (size_t)(w * 128 + mt * 16) * NB);
#pragma unroll
        for (int p2 = 0; p2 < 4; ++p2) {
            const int e   = p2 * 32 + lane;   // uint4 index 0..127
            const int row = e >> 3;
            const int col = e & 7;
            dst[e] = *(const uint4*)(tw + row * TPAD + col * 8);
        }
        __syncwarp();
    }
}

// ---------------------------------------------------------------------------
// c_ij[c][:] = softmax over r of b[c][:]. One block per capsule c; contiguous.
__global__ void __launch_bounds__(256) k_softmax() {
    const int c   = blockIdx.x;
    const int tid = threadIdx.x;
    __shared__ float sm[8];
    const float* bp = g_blog + c * NR;

    float vals[8];
#pragma unroll
    for (int j = 0; j < 8; ++j) vals[j] = bp[tid + j * 256];

    float m = vals[0];
#pragma unroll
    for (int j = 1; j < 8; ++j) m = fmaxf(m, vals[j]);
#pragma unroll
    for (int off = 16; off; off >>= 1) m = fmaxf(m, __shfl_xor_sync(0xffffffffu, m, off));
    if ((tid & 31) == 0) sm[tid >> 5] = m;
    __syncthreads();
    float mm = sm[0];
#pragma unroll
    for (int j = 1; j < 8; ++j) mm = fmaxf(mm, sm[j]);
    __syncthreads();

    float e[8];
    float s = 0.f;
#pragma unroll
    for (int j = 0; j < 8; ++j) { e[j] = expf(vals[j] - mm); s += e[j]; }
#pragma unroll
    for (int off = 16; off; off >>= 1) s += __shfl_xor_sync(0xffffffffu, s, off);
    if ((tid & 31) == 0) sm[tid >> 5] = s;
    __syncthreads();
    float tot = 0.f;
#pragma unroll
    for (int j = 0; j < 8; ++j) tot += sm[j];
    const float inv = 1.f / tot;
    float* cp = g_cij + c * NR;
#pragma unroll
    for (int j = 0; j < 8; ++j) cp[tid + j * 256] = e[j] * inv;
}

// ---------------------------------------------------------------------------
// s partial: block (co2, q) covers routes [q*512, +512). (R12 form.)
__global__ void __launch_bounds__(256) k_s(int uniform) {
    const int co2 = blockIdx.x;
    const int q   = blockIdx.y;
    const int c   = co2 >> 4;
    const int tid = threadIdx.x;
    __shared__ float cs[512];
    __shared__ float red[8][128];

    if (!uniform) {
#pragma unroll
        for (int j = 0; j < 2; ++j)
            cs[tid + j * 256] = g_cij[c * NR + q * 512 + tid + j * 256];
        __syncthreads();
    }

    const int seg  = tid >> 5;
    const int lane = tid & 31;
    const int co_l = lane >> 4;
    const int b4   = (lane & 15) * 4;
    const int r0   = q * 512 + seg * 64;
    const uint2* p = (const uint2*)(g_uhat + (size_t)r0 * RSTRIDE
                                    + (size_t)co2 * 128 + co_l * 64 + b4);
    const float* csp = cs + seg * 64;

    float a0 = 0.f, a1 = 0.f, a2 = 0.f, a3 = 0.f;
#pragma unroll 16
    for (int k = 0; k < 64; ++k) {
        const uint2 u = __ldcs(&p[(size_t)k * (RSTRIDE / 4)]);
        const float2 f0 = __half22float2(*(const __half2*)&u.x);
        const float2 f1 = __half22float2(*(const __half2*)&u.y);
        const float cc = uniform ? C_UNI : csp[k];
        a0 = fmaf(cc, f0.x, a0);
        a1 = fmaf(cc, f0.y, a1);
        a2 = fmaf(cc, f1.x, a2);
        a3 = fmaf(cc, f1.y, a3);
    }
    red[seg][co_l * 64 + b4 + 0] = a0;
    red[seg][co_l * 64 + b4 + 1] = a1;
    red[seg][co_l * 64 + b4 + 2] = a2;
    red[seg][co_l * 64 + b4 + 3] = a3;
    __syncthreads();

    if (tid < 128) {
        float s = 0.f;
#pragma unroll
        for (int j = 0; j < 8; ++j) s += red[j][tid];
        g_spart[(co2 * 4 + q) * 128 + tid] = s;
    }
}

// ---------------------------------------------------------------------------
// Combine quarters, squash -> g_v2 (+ final output on last iter).
__global__ void __launch_bounds__(256) k_red(float* __restrict__ outp) {
    const int idx = blockIdx.x * 256 + threadIdx.x;
    const int co2 = idx >> 7, e = idx & 127;
    const float* pp = g_spart + co2 * 4 * 128 + e;
    const float s = (pp[0] + pp[128]) + (pp[256] + pp[384]);
    const int co = co2 * 2 + (e >> 6);
    const int b  = e & 63;
    const float sq = s * s;
    const float v  = sq * s / ((1.f + sq) * sqrtf(sq));
    g_v2[co * NB + b] = v;
    if (outp) outp[b * NCO + co] = v;
}

// ---------------------------------------------------------------------------
// b[c][r] (+)= (1/B) * sum_{b,o} u_hat[r][c][o][b] * v[c][o][b].
// Warp = (route-group rg of 16, o-quarter oq); 2-deep software pipeline.
__global__ void __launch_bounds__(256) k_a(int first) {
    const int c    = blockIdx.y;
    const int r0   = blockIdx.x * 32;
    const int tid  = threadIdx.x;
    const int lane = tid & 31;
    const int w    = tid >> 5;
    const int oq   = w & 3;
    const int rg   = w >> 2;
    __shared__ __align__(16) float vsm[NO * NB];  // 8 KB
    __shared__ float a_sm[32];

    const float4* vsrc = (const float4*)(g_v2 + c * (NO * NB));
    float4* vdst = (float4*)vsm;
#pragma unroll
    for (int j = 0; j < 2; ++j) vdst[tid + j * 256] = vsrc[tid + j * 256];
    if (tid < 32) a_sm[tid] = 0.f;
    __syncthreads();

    float4 vr[4];
#pragma unroll
    for (int k = 0; k < 2; ++k) {
        const int s = oq * 64 + k * 32 + lane;
        vr[2 * k]     = ((const float4*)vsm)[2 * s];
        vr[2 * k + 1] = ((const float4*)vsm)[2 * s + 1];
    }

    const uint4* const ubase =
        (const uint4*)(g_uhat + (size_t)r0 * RSTRIDE + c * (NO * NB))
        + oq * 64 + lane;
    const size_t rstep = RSTRIDE / 8;

    uint4 u0 = __ldcs(ubase + (size_t)(rg * 16) * rstep);
    uint4 u1 = __ldcs(ubase + (size_t)(rg * 16) * rstep + 32);

#pragma unroll 4
    for (int it = 0; it < 16; ++it) {
        const int rl = rg * 16 + it;
        uint4 n0, n1;
        if (it < 15) {
            n0 = __ldcs(ubase + (size_t)(rl + 1) * rstep);
            n1 = __ldcs(ubase + (size_t)(rl + 1) * rstep + 32);
        }
        float p = 0.f;
        {
            const float2 f0 = __half22float2(*(const __half2*)&u0.x);
            const float2 f1 = __half22float2(*(const __half2*)&u0.y);
            const float2 f2 = __half22float2(*(const __half2*)&u0.z);
            const float2 f3 = __half22float2(*(const __half2*)&u0.w);
            p = fmaf(f0.x, vr[0].x, p); p = fmaf(f0.y, vr[0].y, p);
            p = fmaf(f1.x, vr[0].z, p); p = fmaf(f1.y, vr[0].w, p);
            p = fmaf(f2.x, vr[1].x, p); p = fmaf(f2.y, vr[1].y, p);
            p = fmaf(f3.x, vr[1].z, p); p = fmaf(f3.y, vr[1].w, p);
        }
        {
            const float2 f0 = __half22float2(*(const __half2*)&u1.x);
            const float2 f1 = __half22float2(*(const __half2*)&u1.y);
            const float2 f2 = __half22float2(*(const __half2*)&u1.z);
            const float2 f3 = __half22float2(*(const __half2*)&u1.w);
            p = fmaf(f0.x, vr[2].x, p); p = fmaf(f0.y, vr[2].y, p);
            p = fmaf(f1.x, vr[2].z, p); p = fmaf(f1.y, vr[2].w, p);
            p = fmaf(f2.x, vr[3].x, p); p = fmaf(f2.y, vr[3].y, p);
            p = fmaf(f3.x, vr[3].z, p); p = fmaf(f3.y, vr[3].w, p);
        }
        u0 = n0; u1 = n1;
#pragma unroll
        for (int off = 16; off; off >>= 1) p += __shfl_xor_sync(0xffffffffu, p, off);
        if (lane == 0) atomicAdd(&a_sm[rl], p);
    }
    __syncthreads();

    if (tid < 32) {
        const float val = a_sm[tid] * (1.f / NB);
        if (first) g_blog[c * NR + r0 + tid] = val;
        else       g_blog[c * NR + r0 + tid] += val;
    }
}

// ---------------------------------------------------------------------------
extern "C" void kernel_launch(void* const* d_in, const int* in_sizes, int n_in,
                              void* d_out, int out_size) {
    const float* x = (const float*)d_in[0];  // [B, R, I]
    const float* W = (const float*)d_in[1];  // [R, C, O, I]
    if (n_in >= 2 && in_sizes[0] > in_sizes[1]) {  // robust to input ordering
        const float* t = x; x = W; W = t;
    }
    float* out = (float*)d_out;

    k_uhat<<<NR, 256>>>(x, W);

    // iteration 0: softmax(0) == exactly 1/2048 — skip zero + softmax
    k_s<<<dim3(512, 4), 256>>>(1);
    k_red<<<256, 256>>>(nullptr);
    k_a<<<dim3(64, 32), 256>>>(1);

    // iteration 1
    k_softmax<<<NC, 256>>>();
    k_s<<<dim3(512, 4), 256>>>(0);
    k_red<<<256, 256>>>(nullptr);
    k_a<<<dim3(64, 32), 256>>>(0);

    // iteration 2 (final)
    k_softmax<<<NC, 256>>>();
    k_s<<<dim3(512, 4), 256>>>(0);
    k_red<<<256, 256>>>(out);
}

// round 15
// speedup vs baseline: 1.7263x; 1.0050x over previous
#include <cuda_runtime.h>
#include <cuda_fp16.h>
#include <cstdint>
#include <cstddef>

#define NR 2048
#define NC 32
#define NO 32
#define NI 32
#define NB 64
#define NCO (NC*NO)        // 1024
#define RSTRIDE (NCO*NB)   // 65536 halves per route in u_hat
#define C_UNI (1.0f/2048.0f)
#define TPAD 72            // padded smem tile row stride (halves)

// Scratch (device globals: allocation-free contract)
__device__ __half g_uhat[(size_t)NR * NCO * NB]; // [r][c][o][b]  268 MB fp16
__device__ float  g_spart[256 * 4 * 256];        // k_s partials [co4][q][256]
__device__ float  g_blog[NC * NR];               // routing logits b_ij [c][r]
__device__ float  g_cij[NC * NR];                // softmax(b) over r, [c][r]
__device__ float  g_v2[NCO * NB];                // v in [c][o][b] layout

// ---------------------------------------------------------------------------
__device__ __forceinline__ uint32_t pack_f16x2(float a, float b) {
    uint32_t r;
    asm("cvt.rn.f16x2.f32 %0, %1, %2;" : "=r"(r) : "f"(b), "f"(a));
    return r;
}
// D += A*B (m16n8k16, fp16 in, fp32 acc) — plain mma.sync
__device__ __forceinline__ void mma16816(float* c, const uint32_t* a,
                                         uint32_t b0, uint32_t b1) {
    asm volatile(
        "mma.sync.aligned.m16n8k16.row.col.f32.f16.f16.f32 "
        "{%0,%1,%2,%3},{%4,%5,%6,%7},{%8,%9},{%0,%1,%2,%3};"
        : "+f"(c[0]), "+f"(c[1]), "+f"(c[2]), "+f"(c[3])
        : "r"(a[0]), "r"(a[1]), "r"(a[2]), "r"(a[3]), "r"(b0), "r"(b1));
}

// ---------------------------------------------------------------------------
// u_hat via mma.sync: per route r, D[1024co x 64b] = W_r[1024x32] @ x_r^T.
// Stores staged through padded smem tile -> fully coalesced STG.128 (R14 WIN).
__global__ void __launch_bounds__(256) k_uhat(const float* __restrict__ x,
                                              const float* __restrict__ W) {
    __shared__ __half tile[8][16 * TPAD];   // 8 warps x 16 rows x 72 halves
    const int r    = blockIdx.x;
    const int tid  = threadIdx.x;
    const int w    = tid >> 5;
    const int lane = tid & 31;
    const int g    = lane >> 2;
    const int tg   = lane & 3;

    uint32_t B[8][2][2];
#pragma unroll
    for (int nt = 0; nt < 8; ++nt) {
        const float* xr = x + (size_t)(nt * 8 + g) * (NR * NI) + (size_t)r * NI;
#pragma unroll
        for (int ks = 0; ks < 2; ++ks) {
            const float2 v0 = *(const float2*)(xr + ks * 16 + 2 * tg);
            const float2 v1 = *(const float2*)(xr + ks * 16 + 2 * tg + 8);
            B[nt][ks][0] = pack_f16x2(v0.x, v0.y);
            B[nt][ks][1] = pack_f16x2(v1.x, v1.y);
        }
    }

    const float* wbase = W + (size_t)r * (NCO * NI);
    __half* const ubase = g_uhat + (size_t)r * RSTRIDE;

#pragma unroll 1
    for (int mt = 0; mt < 8; ++mt) {
        const int co0 = w * 128 + mt * 16 + g;
        const float* wr0 = wbase + (size_t)co0 * NI;
        const float* wr1 = wr0 + 8 * NI;

        uint32_t A[2][4];
#pragma unroll
        for (int ks = 0; ks < 2; ++ks) {
            float2 v;
            v = *(const float2*)(wr0 + ks * 16 + 2 * tg);     A[ks][0] = pack_f16x2(v.x, v.y);
            v = *(const float2*)(wr1 + ks * 16 + 2 * tg);     A[ks][1] = pack_f16x2(v.x, v.y);
            v = *(const float2*)(wr0 + ks * 16 + 2 * tg + 8); A[ks][2] = pack_f16x2(v.x, v.y);
            v = *(const float2*)(wr1 + ks * 16 + 2 * tg + 8); A[ks][3] = pack_f16x2(v.x, v.y);
        }

        __half* const tw = tile[w];
#pragma unroll
        for (int nt = 0; nt < 8; ++nt) {
            float acc[4] = {0.f, 0.f, 0.f, 0.f};
            mma16816(acc, A[0], B[nt][0][0], B[nt][0][1]);
            mma16816(acc, A[1], B[nt][1][0], B[nt][1][1]);
            const int b0 = nt * 8 + 2 * tg;
            *(__half2*)(tw + g * TPAD + b0)       = __floats2half2_rn(acc[0], acc[1]);
            *(__half2*)(tw + (g + 8) * TPAD + b0) = __floats2half2_rn(acc[2], acc[3]);
        }
        __syncwarp();

        uint4* dst = (uint4*)(ubase + (size_t)(w * 128 + mt * 16) * NB);
#pragma unroll
        for (int p2 = 0; p2 < 4; ++p2) {
            const int e   = p2 * 32 + lane;
            const int row = e >> 3;
            const int col = e & 7;
            dst[e] = *(const uint4*)(tw + row * TPAD + col * 8);
        }
        __syncwarp();
    }
}

// ---------------------------------------------------------------------------
// c_ij[c][:] = softmax over r of b[c][:]. One block per capsule c; contiguous.
__global__ void __launch_bounds__(256) k_softmax() {
    const int c   = blockIdx.x;
    const int tid = threadIdx.x;
    __shared__ float sm[8];
    const float* bp = g_blog + c * NR;

    float vals[8];
#pragma unroll
    for (int j = 0; j < 8; ++j) vals[j] = bp[tid + j * 256];

    float m = vals[0];
#pragma unroll
    for (int j = 1; j < 8; ++j) m = fmaxf(m, vals[j]);
#pragma unroll
    for (int off = 16; off; off >>= 1) m = fmaxf(m, __shfl_xor_sync(0xffffffffu, m, off));
    if ((tid & 31) == 0) sm[tid >> 5] = m;
    __syncthreads();
    float mm = sm[0];
#pragma unroll
    for (int j = 1; j < 8; ++j) mm = fmaxf(mm, sm[j]);
    __syncthreads();

    float e[8];
    float s = 0.f;
#pragma unroll
    for (int j = 0; j < 8; ++j) { e[j] = expf(vals[j] - mm); s += e[j]; }
#pragma unroll
    for (int off = 16; off; off >>= 1) s += __shfl_xor_sync(0xffffffffu, s, off);
    if ((tid & 31) == 0) sm[tid >> 5] = s;
    __syncthreads();
    float tot = 0.f;
#pragma unroll
    for (int j = 0; j < 8; ++j) tot += sm[j];
    const float inv = 1.f / tot;
    float* cp = g_cij + c * NR;
#pragma unroll
    for (int j = 0; j < 8; ++j) cp[tid + j * 256] = e[j] * inv;
}

// ---------------------------------------------------------------------------
// s partial: block (co4, q) covers co quad [co4*4,+4) and routes [q*512,+512).
// Warp = seg of 64 routes; lane reads one uint4 (16B) per route — warp covers
// the quad's full 512B row. 8 fp32 accumulators; e = lane*8+j element mapping.
__global__ void __launch_bounds__(256) k_s(int uniform) {
    const int co4 = blockIdx.x;          // 0..255
    const int q   = blockIdx.y;          // 0..3
    const int c   = co4 >> 3;
    const int tid = threadIdx.x;
    __shared__ float cs[512];
    __shared__ float red[8][256];

    if (!uniform) {
#pragma unroll
        for (int j = 0; j < 2; ++j)
            cs[tid + j * 256] = g_cij[c * NR + q * 512 + tid + j * 256];
        __syncthreads();
    }

    const int seg  = tid >> 5;
    const int lane = tid & 31;
    const int r0   = q * 512 + seg * 64;
    const uint4* p = (const uint4*)(g_uhat + (size_t)r0 * RSTRIDE)
                     + co4 * 32 + lane;
    const float* csp = cs + seg * 64;

    float acc[8] = {0.f, 0.f, 0.f, 0.f, 0.f, 0.f, 0.f, 0.f};
#pragma unroll 16
    for (int k = 0; k < 64; ++k) {
        const uint4 u = __ldcs(&p[(size_t)k * (RSTRIDE / 8)]);
        const float cc = uniform ? C_UNI : csp[k];
        const float2 f0 = __half22float2(*(const __half2*)&u.x);
        const float2 f1 = __half22float2(*(const __half2*)&u.y);
        const float2 f2 = __half22float2(*(const __half2*)&u.z);
        const float2 f3 = __half22float2(*(const __half2*)&u.w);
        acc[0] = fmaf(cc, f0.x, acc[0]);
        acc[1] = fmaf(cc, f0.y, acc[1]);
        acc[2] = fmaf(cc, f1.x, acc[2]);
        acc[3] = fmaf(cc, f1.y, acc[3]);
        acc[4] = fmaf(cc, f2.x, acc[4]);
        acc[5] = fmaf(cc, f2.y, acc[5]);
        acc[6] = fmaf(cc, f3.x, acc[6]);
        acc[7] = fmaf(cc, f3.y, acc[7]);
    }
    *(float4*)&red[seg][lane * 8]     = make_float4(acc[0], acc[1], acc[2], acc[3]);
    *(float4*)&red[seg][lane * 8 + 4] = make_float4(acc[4], acc[5], acc[6], acc[7]);
    __syncthreads();

    float s = 0.f;
#pragma unroll
    for (int j = 0; j < 8; ++j) s += red[j][tid];
    g_spart[(co4 * 4 + q) * 256 + tid] = s;
}

// ---------------------------------------------------------------------------
// Combine quarters, squash -> g_v2 (+ final output on last iter).
__global__ void __launch_bounds__(256) k_red(float* __restrict__ outp) {
    const int idx = blockIdx.x * 256 + threadIdx.x;   // co4*256 + e  (65536)
    const int co4 = idx >> 8, e = idx & 255;
    const float* pp = g_spart + co4 * 4 * 256 + e;
    const float s = (pp[0] + pp[256]) + (pp[512] + pp[768]);
    const int co = co4 * 4 + (e >> 6);
    const int b  = e & 63;
    const float sq = s * s;
    const float v  = sq * s / ((1.f + sq) * sqrtf(sq));
    g_v2[co * NB + b] = v;                 // [c][o][b] for the a-pass
    if (outp) outp[b * NCO + co] = v;      // [b][c][o][1] final output
}

// ---------------------------------------------------------------------------
// b[c][r] (+)= (1/B) * sum_{b,o} u_hat[r][c][o][b] * v[c][o][b].
// Warp = (route-group rg of 16, o-quarter oq); 2-deep software pipeline.
// (R14 form — unchanged.)
__global__ void __launch_bounds__(256) k_a(int first) {
    const int c    = blockIdx.y;
    const int r0   = blockIdx.x * 32;
    const int tid  = threadIdx.x;
    const int lane = tid & 31;
    const int w    = tid >> 5;
    const int oq   = w & 3;
    const int rg   = w >> 2;
    __shared__ __align__(16) float vsm[NO * NB];  // 8 KB
    __shared__ float a_sm[32];

    const float4* vsrc = (const float4*)(g_v2 + c * (NO * NB));
    float4* vdst = (float4*)vsm;
#pragma unroll
    for (int j = 0; j < 2; ++j) vdst[tid + j * 256] = vsrc[tid + j * 256];
    if (tid < 32) a_sm[tid] = 0.f;
    __syncthreads();

    float4 vr[4];
#pragma unroll
    for (int k = 0; k < 2; ++k) {
        const int s = oq * 64 + k * 32 + lane;
        vr[2 * k]     = ((const float4*)vsm)[2 * s];
        vr[2 * k + 1] = ((const float4*)vsm)[2 * s + 1];
    }

    const uint4* const ubase =
        (const uint4*)(g_uhat + (size_t)r0 * RSTRIDE + c * (NO * NB))
        + oq * 64 + lane;
    const size_t rstep = RSTRIDE / 8;

    uint4 u0 = __ldcs(ubase + (size_t)(rg * 16) * rstep);
    uint4 u1 = __ldcs(ubase + (size_t)(rg * 16) * rstep + 32);

#pragma unroll 4
    for (int it = 0; it < 16; ++it) {
        const int rl = rg * 16 + it;
        uint4 n0, n1;
        if (it < 15) {
            n0 = __ldcs(ubase + (size_t)(rl + 1) * rstep);
            n1 = __ldcs(ubase + (size_t)(rl + 1) * rstep + 32);
        }
        float p = 0.f;
        {
            const float2 f0 = __half22float2(*(const __half2*)&u0.x);
            const float2 f1 = __half22float2(*(const __half2*)&u0.y);
            const float2 f2 = __half22float2(*(const __half2*)&u0.z);
            const float2 f3 = __half22float2(*(const __half2*)&u0.w);
            p = fmaf(f0.x, vr[0].x, p); p = fmaf(f0.y, vr[0].y, p);
            p = fmaf(f1.x, vr[0].z, p); p = fmaf(f1.y, vr[0].w, p);
            p = fmaf(f2.x, vr[1].x, p); p = fmaf(f2.y, vr[1].y, p);
            p = fmaf(f3.x, vr[1].z, p); p = fmaf(f3.y, vr[1].w, p);
        }
        {
            const float2 f0 = __half22float2(*(const __half2*)&u1.x);
            const float2 f1 = __half22float2(*(const __half2*)&u1.y);
            const float2 f2 = __half22float2(*(const __half2*)&u1.z);
            const float2 f3 = __half22float2(*(const __half2*)&u1.w);
            p = fmaf(f0.x, vr[2].x, p); p = fmaf(f0.y, vr[2].y, p);
            p = fmaf(f1.x, vr[2].z, p); p = fmaf(f1.y, vr[2].w, p);
            p = fmaf(f2.x, vr[3].x, p); p = fmaf(f2.y, vr[3].y, p);
            p = fmaf(f3.x, vr[3].z, p); p = fmaf(f3.y, vr[3].w, p);
        }
        u0 = n0; u1 = n1;
#pragma unroll
        for (int off = 16; off; off >>= 1) p += __shfl_xor_sync(0xffffffffu, p, off);
        if (lane == 0) atomicAdd(&a_sm[rl], p);
    }
    __syncthreads();

    if (tid < 32) {
        const float val = a_sm[tid] * (1.f / NB);
        if (first) g_blog[c * NR + r0 + tid] = val;
        else       g_blog[c * NR + r0 + tid] += val;
    }
}

// ---------------------------------------------------------------------------
extern "C" void kernel_launch(void* const* d_in, const int* in_sizes, int n_in,
                              void* d_out, int out_size) {
    const float* x = (const float*)d_in[0];  // [B, R, I]
    const float* W = (const float*)d_in[1];  // [R, C, O, I]
    if (n_in >= 2 && in_sizes[0] > in_sizes[1]) {  // robust to input ordering
        const float* t = x; x = W; W = t;
    }
    float* out = (float*)d_out;

    k_uhat<<<NR, 256>>>(x, W);

    // iteration 0: softmax(0) == exactly 1/2048 — skip zero + softmax
    k_s<<<dim3(256, 4), 256>>>(1);
    k_red<<<256, 256>>>(nullptr);
    k_a<<<dim3(64, 32), 256>>>(1);

    // iteration 1
    k_softmax<<<NC, 256>>>();
    k_s<<<dim3(256, 4), 256>>>(0);
    k_red<<<256, 256>>>(nullptr);
    k_a<<<dim3(64, 32), 256>>>(0);

    // iteration 2 (final)
    k_softmax<<<NC, 256>>>();
    k_s<<<dim3(256, 4), 256>>>(0);
    k_red<<<256, 256>>>(out);
}